// round 1
// baseline (speedup 1.0000x reference)
#include <cuda_runtime.h>
#include <stdint.h>

#define NB 32
#define NT 15

// Scratch (no cudaMalloc allowed) — all fully rewritten every launch.
static __device__ int8_t g_tf0 [NB*18*32*32];   // input fire times
static __device__ int8_t g_ft1 [NB*90*30*30];   // layer1 fire times
static __device__ int8_t g_ft1p[NB*90*17*17];   // pooled(2,2)+pad(1)
static __device__ int8_t g_ft2 [NB*250*13*13];  // layer2 fire times
static __device__ int8_t g_ft2p[NB*250*8*8];    // pooled(3,3)+pad(2)

// ---------------------------------------------------------------------------
// Input is cumulative (t >= t_fire), so sum over t = 15 - t_fire.
__global__ void k_tf0(const float* __restrict__ inp) {
    int idx = blockIdx.x * 256 + threadIdx.x;
    if (idx >= NB*18*32*32) return;
    int b   = idx / (18*1024);
    int chw = idx - b * (18*1024);
    const float* p = inp + (size_t)b * (NT*18*1024) + chw;
    float s = 0.0f;
#pragma unroll
    for (int t = 0; t < NT; t++) s += p[(size_t)t * 18 * 1024];
    g_tf0[idx] = (int8_t)(15 - (int)(s + 0.5f));
}

// ---------------------------------------------------------------------------
// conv1: (B,18,36,36 padded) -> (B,90,30,30), thr 15, output = fire time
__global__ __launch_bounds__(256) void k_conv1(const float* __restrict__ w1) {
    __shared__ int8_t s_tf[18*14*36];
    __shared__ float  s_w[882];
    __shared__ float  s_h[14*256];     // bins 1..14 (bin0->reg, bin15 skipped)
    int tid = threadIdx.y * 32 + threadIdx.x;
    int ys = blockIdx.x, f = blockIdx.y, b = blockIdx.z;

    for (int i = tid; i < 882; i += 256) s_w[i] = w1[f*882 + i];
    for (int i = tid; i < 18*14*36; i += 256) {
        int c = i / (14*36);
        int rem = i - c * (14*36);
        int r = rem / 36, col = rem - r * 36;
        int h = ys*8 + r - 2, w = col - 2;   // pad=2
        int8_t v = 15;
        if ((unsigned)h < 32u && (unsigned)w < 32u)
            v = g_tf0[((b*18 + c)*32 + h)*32 + w];
        s_tf[i] = v;
    }
    float* hb = s_h + tid;
#pragma unroll
    for (int t = 0; t < 14; t++) hb[t*256] = 0.0f;
    __syncthreads();

    int x = threadIdx.x, y = ys*8 + threadIdx.y;
    if (x < 30 && y < 30) {
        float a0 = 0.0f;
        for (int c = 0; c < 18; c++) {
#pragma unroll
            for (int i = 0; i < 7; i++) {
                const int8_t* row = s_tf + (c*14 + threadIdx.y + i)*36 + x;
                const float*  wr  = s_w + (c*7 + i)*7;
#pragma unroll
                for (int j = 0; j < 7; j++) {
                    int tf = row[j];
                    float w = wr[j];
                    if (tf == 0)      a0 += w;
                    else if (tf < 15) hb[(tf-1)*256] += w;
                }
            }
        }
        float cum = a0; int ft = 15;
        if (cum > 15.0f) ft = 0;
#pragma unroll
        for (int t = 1; t < 15; t++) {
            cum += hb[(t-1)*256];
            if (ft == 15 && cum > 15.0f) ft = t;
        }
        g_ft1[((b*90 + f)*30 + y)*30 + x] = (int8_t)ft;
    }
}

// ---------------------------------------------------------------------------
// pool 2x2 s2 (min of fire times) + pad 1 with "never" (15)
__global__ void k_pool1() {
    int idx = blockIdx.x * 256 + threadIdx.x;
    if (idx >= NB*90*17*17) return;
    int px = idx % 17;
    int t1 = idx / 17;
    int py = t1 % 17;
    int bf = t1 / 17;
    int v = 15;
    if (py >= 1 && py <= 15 && px >= 1 && px <= 15) {
        int qy = (py-1)*2, qx = (px-1)*2;
        const int8_t* base = g_ft1 + (bf*30 + qy)*30 + qx;
        int v0 = base[0],  v1 = base[1];
        int v2 = base[30], v3 = base[31];
        v = v0 < v1 ? v0 : v1;
        int w2_ = v2 < v3 ? v2 : v3;
        v = v < w2_ ? v : w2_;
    }
    g_ft1p[idx] = (int8_t)v;
}

// ---------------------------------------------------------------------------
// conv2: (B,90,17,17) -> (B,250,13,13), thr 10
__global__ __launch_bounds__(192) void k_conv2(const float* __restrict__ w2) {
    __shared__ int8_t s_tf[90*289];
    __shared__ float  s_w[2250];
    __shared__ float  s_h[14*192];
    int tid = threadIdx.x;
    int f = blockIdx.x, b = blockIdx.y;

    for (int i = tid; i < 2250;   i += 192) s_w[i]  = w2[f*2250 + i];
    for (int i = tid; i < 90*289; i += 192) s_tf[i] = g_ft1p[b*(90*289) + i];
    float* hb = s_h + tid;
#pragma unroll
    for (int t = 0; t < 14; t++) hb[t*192] = 0.0f;
    __syncthreads();

    if (tid < 169) {
        int y = tid / 13, x = tid - y*13;
        float a0 = 0.0f;
        for (int c = 0; c < 90; c++) {
#pragma unroll
            for (int i = 0; i < 5; i++) {
                const int8_t* row = s_tf + c*289 + (y+i)*17 + x;
                const float*  wr  = s_w + c*25 + i*5;
#pragma unroll
                for (int j = 0; j < 5; j++) {
                    int tf = row[j];
                    float w = wr[j];
                    if (tf == 0)      a0 += w;
                    else if (tf < 15) hb[(tf-1)*192] += w;
                }
            }
        }
        float cum = a0; int ft = 15;
        if (cum > 10.0f) ft = 0;
#pragma unroll
        for (int t = 1; t < 15; t++) {
            cum += hb[(t-1)*192];
            if (ft == 15 && cum > 10.0f) ft = t;
        }
        g_ft2[(b*250 + f)*169 + tid] = (int8_t)ft;
    }
}

// ---------------------------------------------------------------------------
// pool 3x3 s3 (min) + pad 2 with 15  -> (B,250,8,8)
__global__ void k_pool2() {
    int idx = blockIdx.x * 256 + threadIdx.x;
    if (idx >= NB*250*64) return;
    int px = idx & 7, py = (idx >> 3) & 7, bc = idx >> 6;
    int v = 15;
    if (py >= 2 && py <= 5 && px >= 2 && px <= 5) {
        int qy = (py-2)*3, qx = (px-2)*3;
        const int8_t* base = g_ft2 + bc*169 + qy*13 + qx;
#pragma unroll
        for (int dy = 0; dy < 3; dy++)
#pragma unroll
            for (int dx = 0; dx < 3; dx++) {
                int u = base[dy*13 + dx];
                v = u < v ? u : v;
            }
    }
    g_ft2p[idx] = (int8_t)v;
}

// ---------------------------------------------------------------------------
// conv3: (B,250,8,8) -> pot3 (B,T,200,4,4) via 16-bin histogram + prefix sum
__global__ __launch_bounds__(256) void k_conv3(const float* __restrict__ w3,
                                               float* __restrict__ pot) {
    __shared__ int8_t s_tf[250*64];
    __shared__ float  s_h[14*256];
    int tid = threadIdx.x;
    int fg = blockIdx.x, b = blockIdx.y;

    for (int i = tid; i < 250*64; i += 256) s_tf[i] = g_ft2p[b*(250*64) + i];
    float* hb = s_h + tid;
#pragma unroll
    for (int t = 0; t < 14; t++) hb[t*256] = 0.0f;
    __syncthreads();

    int fi = tid >> 4, pos = tid & 15;
    int f = fg*16 + fi;
    if (f < 200) {
        int y = pos >> 2, x = pos & 3;
        float a0 = 0.0f;
        const float* wf = w3 + (size_t)f * 6250;
        for (int c = 0; c < 250; c++) {
            const int8_t* tb = s_tf + c*64 + y*8 + x;
            const float*  wr = wf + c*25;
#pragma unroll
            for (int i = 0; i < 5; i++) {
#pragma unroll
                for (int j = 0; j < 5; j++) {
                    int tf = tb[i*8 + j];
                    float w = __ldg(wr + i*5 + j);
                    if (tf == 0)      a0 += w;
                    else if (tf < 15) hb[(tf-1)*256] += w;
                }
            }
        }
        float cum = a0;
        float* o = pot + ((size_t)b*NT*200 + f)*16 + pos;
#pragma unroll
        for (int t = 0; t < 15; t++) {
            if (t > 0) cum += hb[(t-1)*256];
            o[(size_t)t * 3200] = cum;   // (B,T,200,4,4): t-stride = 200*16
        }
    }
}

// ---------------------------------------------------------------------------
// winner class: among pot3[:,14] > 0 pick max (first index on ties);
// class = (flat_idx / 16) / 20, or -1 if no spike.
__global__ void k_winner(const float* __restrict__ pot, float* __restrict__ cls) {
    __shared__ float s_v[256];
    __shared__ int   s_i[256];
    int b = blockIdx.x, tid = threadIdx.x;
    const float* p = pot + ((size_t)b*NT + 14) * 3200;
    float bv = 0.0f; int bi = 1 << 30;
    for (int i = tid; i < 3200; i += 256) {
        float v = p[i];
        if (v > bv) { bv = v; bi = i; }   // strict > keeps earliest index
    }
    s_v[tid] = bv; s_i[tid] = bi;
    __syncthreads();
    for (int s = 128; s > 0; s >>= 1) {
        if (tid < s) {
            float ov = s_v[tid+s]; int oi = s_i[tid+s];
            if (ov > s_v[tid] || (ov == s_v[tid] && oi < s_i[tid])) {
                s_v[tid] = ov; s_i[tid] = oi;
            }
        }
        __syncthreads();
    }
    if (tid == 0)
        cls[b] = (s_v[0] > 0.0f) ? (float)((s_i[0] >> 4) / 20) : -1.0f;
}

// ---------------------------------------------------------------------------
extern "C" void kernel_launch(void* const* d_in, const int* in_sizes, int n_in,
                              void* d_out, int out_size) {
    const float* inp = (const float*)d_in[0];
    const float* w1  = (const float*)d_in[1];
    const float* w2  = (const float*)d_in[2];
    const float* w3  = (const float*)d_in[3];
    // d_in[4] = max_layer (always 3 for this problem)

    float* out = (float*)d_out;
    float* pot = out;
    float* cls = nullptr;
    if (out_size == NB + NB*NT*3200) {      // (cls, pot3) concatenated
        cls = out;
        pot = out + NB;
    }                                        // else: pot3-only layout

    k_tf0  <<<(NB*18*1024 + 255)/256, 256>>>(inp);
    k_conv1<<<dim3(4, 90, NB), dim3(32, 8)>>>(w1);
    k_pool1<<<(NB*90*289 + 255)/256, 256>>>();
    k_conv2<<<dim3(250, NB), 192>>>(w2);
    k_pool2<<<(NB*250*64 + 255)/256, 256>>>();
    k_conv3<<<dim3(13, NB), 256>>>(w3, pot);
    if (cls) k_winner<<<NB, 256>>>(pot, cls);
}

// round 2
// speedup vs baseline: 22.8692x; 22.8692x over previous
#include <cuda_runtime.h>
#include <stdint.h>

#define NB 32
#define NT 15

// ---------------- device scratch (no cudaMalloc allowed) ----------------
static __device__ __align__(16) int8_t g_tf0 [NB*18*32*32];    // input fire times
static __device__ __align__(16) int8_t g_ft1 [NB*90*30*30];    // layer1 fire times
static __device__ __align__(16) int8_t g_ft1p[NB*90*15*16];    // pooled, row-stride 16, filler=0
static __device__ __align__(16) int8_t g_ft2 [NB*250*13*13];   // layer2 fire times
static __device__ __align__(16) int8_t g_ft2p[NB*250*16];      // pooled 4x4
static __device__ __align__(16) float  g_w1q [12*882*8];       // w1 repacked, 8 filters interleaved
static __device__            float  g_wsat2[250*36];           // SAT of channel-summed w2 kernels
static __device__            float  g_wsat3[200*36];           // SAT of channel-summed w3 kernels

// ---------------------------------------------------------------------------
// Input is cumulative (t >= t_fire): fire time = 15 - sum_t.
__global__ void k_tf0(const float* __restrict__ inp) {
    int idx = blockIdx.x * 256 + threadIdx.x;
    if (idx >= NB*18*32*32) return;
    int b   = idx / (18*1024);
    int chw = idx - b * (18*1024);
    const float* p = inp + (size_t)b * (NT*18*1024) + chw;
    float s = 0.0f;
#pragma unroll
    for (int t = 0; t < NT; t++) s += p[(size_t)t * 18 * 1024];
    g_tf0[idx] = (int8_t)(15 - (int)(s + 0.5f));
}

// ---------------------------------------------------------------------------
// Repack w1 (90,18,7,7) into [fq][k][8] quad-interleaved (f = fq*8+q), zero-pad.
__global__ void k_wrep1(const float* __restrict__ w1) {
    int idx = blockIdx.x * 256 + threadIdx.x;
    if (idx >= 12*882*8) return;
    int q  = idx & 7;
    int k  = (idx >> 3) % 882;
    int fq = idx / (882*8);
    int f  = fq*8 + q;
    g_w1q[idx] = (f < 90) ? w1[f*882 + k] : 0.0f;
}

// ---------------------------------------------------------------------------
// SAT of channel-summed 5x5 kernels. One block per filter.
__global__ void k_wsat2(const float* __restrict__ w2) {
    __shared__ float ws[25];
    int f = blockIdx.x, l = threadIdx.x;
    if (l < 25) {
        float s = 0.0f;
        for (int c = 0; c < 90; c++) s += w2[(f*90 + c)*25 + l];
        ws[l] = s;
    }
    __syncwarp();
    for (int e = l; e < 36; e += 32) {
        int i = e / 6, j = e % 6;
        float s = 0.0f;
        for (int ii = 0; ii < i; ii++)
            for (int jj = 0; jj < j; jj++) s += ws[ii*5 + jj];
        g_wsat2[f*36 + e] = s;
    }
}
__global__ void k_wsat3(const float* __restrict__ w3) {
    __shared__ float ws[25];
    int f = blockIdx.x, l = threadIdx.x;
    if (l < 25) {
        float s = 0.0f;
        for (int c = 0; c < 250; c++) s += w3[(f*250 + c)*25 + l];
        ws[l] = s;
    }
    __syncwarp();
    for (int e = l; e < 36; e += 32) {
        int i = e / 6, j = e % 6;
        float s = 0.0f;
        for (int ii = 0; ii < i; ii++)
            for (int jj = 0; jj < j; jj++) s += ws[ii*5 + jj];
        g_wsat3[f*36 + e] = s;
    }
}

// ---------------------------------------------------------------------------
// conv1 slow path (rare): full per-t rescan for one filter q of the 8-group.
__device__ __noinline__ int conv1_slow(const int8_t* tb, const float* sw, int q) {
    for (int t = 1; t < 15; t++) {
        float cum = 0.0f;
        for (int c = 0; c < 18; c++)
            for (int i = 0; i < 7; i++)
                for (int j = 0; j < 7; j++) {
                    int tf = tb[c*504 + i*36 + j];
                    if (tf <= t) cum += sw[(c*49 + i*7 + j)*8 + q];
                }
        if (cum > 15.0f) return t;
    }
    return 15;
}

// conv1: (B,18,36,36 padded) -> fire times (B,90,30,30). 8 filters per block.
// Fast path: only pot(0) (tf==0 terms). Slow rescan if pot(0) <= thr.
__global__ __launch_bounds__(256) void k_conv1() {
    __shared__ __align__(16) int8_t s_tf[18*14*36];   // 9072 B
    __shared__ __align__(16) float  s_w[882*8];       // 28224 B
    int tx = threadIdx.x, ty = threadIdx.y;           // 32 x 8
    int tid = ty*32 + tx;
    int ys = blockIdx.x, fq = blockIdx.y, b = blockIdx.z;

    const float* wsrc = g_w1q + fq*882*8;
    for (int i = tid; i < 882*8; i += 256) s_w[i] = wsrc[i];
    for (int i = tid; i < 18*14*36; i += 256) {
        int c = i / 504;
        int rem = i - c*504;
        int r = rem / 36, col = rem - r*36;
        int h = ys*8 + r - 2, w = col - 2;            // pad = 2
        int8_t v = 15;
        if ((unsigned)h < 32u && (unsigned)w < 32u)
            v = g_tf0[((b*18 + c) << 10) + (h << 5) + w];
        s_tf[i] = v;
    }
    __syncthreads();

    int x = tx, y = ys*8 + ty;
    if (x >= 30 || y >= 30) return;

    float a0=0,a1=0,a2=0,a3=0,a4=0,a5=0,a6=0,a7=0;
    const int8_t* tbase = s_tf + ty*36 + tx;
    for (int c = 0; c < 18; c++) {
        const int8_t* cb = tbase + c*504;
        const float*  wc = s_w + c*49*8;
#pragma unroll
        for (int i = 0; i < 7; i++) {
            const int8_t* row = cb + i*36;
            const float*  wr  = wc + i*7*8;
#pragma unroll
            for (int j = 0; j < 7; j++) {
                if (row[j] == 0) {
                    float4 wa = *(const float4*)(wr + j*8);
                    float4 wb = *(const float4*)(wr + j*8 + 4);
                    a0 += wa.x; a1 += wa.y; a2 += wa.z; a3 += wa.w;
                    a4 += wb.x; a5 += wb.y; a6 += wb.z; a7 += wb.w;
                }
            }
        }
    }
    float a[8] = {a0,a1,a2,a3,a4,a5,a6,a7};
    int f0 = fq*8;
#pragma unroll
    for (int q = 0; q < 8; q++) {
        int f = f0 + q;
        if (f < 90) {
            int ft = (a[q] > 15.0f) ? 0 : conv1_slow(tbase, s_w, q);
            g_ft1[((b*90 + f)*30 + y)*30 + x] = (int8_t)ft;
        }
    }
}

// ---------------------------------------------------------------------------
// pool 2x2 s2 (min of fire times), output row-stride 16, filler byte = 0.
__global__ void k_pool1() {
    int idx = blockIdx.x * 256 + threadIdx.x;
    if (idx >= NB*90*15*16) return;
    int col = idx & 15;
    int t   = idx >> 4;
    int row = t % 15;
    int bc  = t / 15;
    int8_t v = 0;                       // filler (never read by rects, keeps flags clean)
    if (col < 15) {
        const int8_t* base = g_ft1 + bc*900 + row*60 + col*2;
        int v0 = base[0],  v1 = base[1];
        int v2 = base[30], v3 = base[31];
        int m0 = v0 < v1 ? v0 : v1;
        int m1 = v2 < v3 ? v2 : v3;
        v = (int8_t)(m0 < m1 ? m0 : m1);
    }
    g_ft1p[idx] = v;
}

// ---------------------------------------------------------------------------
// conv2: SAT fast path + per-channel corrections. thr 10.
__global__ __launch_bounds__(192) void k_conv2(const float* __restrict__ w2) {
    __shared__ __align__(16) int8_t s_tf[90*240];   // 21600 B
    __shared__ float s_sat[36];
    __shared__ float s_h[14*192];                   // histogram (fallback only)
    __shared__ int   s_flags[96];
    __shared__ int   s_any;
    int tid = threadIdx.x;
    int f = blockIdx.x, b = blockIdx.y;

    const uint4* src = (const uint4*)(g_ft1p + (size_t)b*90*240);
    uint4* dst = (uint4*)s_tf;
    for (int i = tid; i < 90*240/16; i += 192) dst[i] = src[i];
    if (tid < 36) s_sat[tid] = g_wsat2[f*36 + tid];
    if (tid == 0) s_any = 0;
    if (tid < 96) s_flags[tid] = 0;
    __syncthreads();

    if (tid < 90) {
        const unsigned* p = (const unsigned*)(s_tf + tid*240);
        unsigned o = 0;
#pragma unroll
        for (int k = 0; k < 60; k++) o |= p[k];
        if (o) { s_flags[tid] = 1; atomicAdd(&s_any, 1); }
    }
    for (int t = 0; t < 14; t++) s_h[t*192 + tid] = 0.0f;
    __syncthreads();

    int any = s_any;
    if (tid < 169) {
        int y = tid / 13, x = tid - y*13;
        int r0 = max(0, y-1), r1 = min(14, y+3);
        int c0 = max(0, x-1), c1 = min(14, x+3);
        int i0 = r0 - (y-1), i1 = r1 - (y-1);
        int j0 = c0 - (x-1), j1 = c1 - (x-1);
        float a0 = s_sat[(i1+1)*6 + (j1+1)] - s_sat[i0*6 + (j1+1)]
                 - s_sat[(i1+1)*6 + j0]     + s_sat[i0*6 + j0];
        int ft;
        if (any == 0) {
            ft = (a0 > 10.0f) ? 0 : 15;
        } else {
            float* hb = s_h + tid;
            for (int c = 0; c < 90; c++) {
                if (!s_flags[c]) continue;
                const int8_t* tp = s_tf + c*240;
                const float*  wp = w2 + (f*90 + c)*25;
                for (int r = r0; r <= r1; r++)
                    for (int cc = c0; cc <= c1; cc++) {
                        int tf = tp[r*16 + cc];
                        if (tf) {
                            float w = __ldg(wp + (r-(y-1))*5 + (cc-(x-1)));
                            a0 -= w;
                            if (tf < 15) hb[(tf-1)*192] += w;
                        }
                    }
            }
            float cum = a0; ft = 15;
            if (cum > 10.0f) ft = 0;
#pragma unroll
            for (int t = 1; t < 15; t++) {
                cum += hb[(t-1)*192];
                if (ft == 15 && cum > 10.0f) ft = t;
            }
        }
        g_ft2[(b*250 + f)*169 + tid] = (int8_t)ft;
    }
}

// ---------------------------------------------------------------------------
// pool 3x3 s3 (min) -> (B,250,4,4) unpadded.
__global__ void k_pool2() {
    int idx = blockIdx.x * 256 + threadIdx.x;
    if (idx >= NB*250*16) return;
    int x = idx & 3, y = (idx >> 2) & 3, bc = idx >> 4;
    const int8_t* base = g_ft2 + bc*169 + y*39 + x*3;
    int v = 15;
#pragma unroll
    for (int dy = 0; dy < 3; dy++)
#pragma unroll
        for (int dx = 0; dx < 3; dx++) {
            int u = base[dy*13 + dx];
            v = u < v ? u : v;
        }
    g_ft2p[idx] = (int8_t)v;
}

// ---------------------------------------------------------------------------
// conv3: SAT fast path + corrections; writes full pot3 (B,T,200,4,4).
__global__ __launch_bounds__(256) void k_conv3(const float* __restrict__ w3,
                                               float* __restrict__ pot) {
    __shared__ __align__(16) int8_t s_tf[250*16];   // 4000 B
    __shared__ float s_sat[16*36];
    __shared__ float s_h[14*256];
    __shared__ int   s_flags[256];
    __shared__ int   s_any;
    int tid = threadIdx.x;
    int fg = blockIdx.x, b = blockIdx.y;

    const uint4* src = (const uint4*)(g_ft2p + (size_t)b*250*16);
    for (int i = tid; i < 250; i += 256) ((uint4*)s_tf)[i] = src[i];
    for (int i = tid; i < 16*36; i += 256) {
        int f = fg*16 + i/36;
        s_sat[i] = (f < 200) ? g_wsat3[f*36 + i%36] : 0.0f;
    }
    if (tid == 0) s_any = 0;
    s_flags[tid] = 0;
    __syncthreads();

    if (tid < 250) {
        uint4 v = ((const uint4*)s_tf)[tid];
        if (v.x | v.y | v.z | v.w) { s_flags[tid] = 1; atomicAdd(&s_any, 1); }
    }
    for (int t = 0; t < 14; t++) s_h[t*256 + tid] = 0.0f;
    __syncthreads();

    int any = s_any;
    int fi = tid >> 4, p = tid & 15;
    int f = fg*16 + fi;
    if (f < 200) {
        int y = p >> 2, x = p & 3;
        int r0 = max(0, y-2), r1 = min(3, y+2);
        int c0 = max(0, x-2), c1 = min(3, x+2);
        int i0 = r0 - (y-2), i1 = r1 - (y-2);
        int j0 = c0 - (x-2), j1 = c1 - (x-2);
        const float* S = s_sat + fi*36;
        float a0 = S[(i1+1)*6 + (j1+1)] - S[i0*6 + (j1+1)]
                 - S[(i1+1)*6 + j0]     + S[i0*6 + j0];
        float* o = pot + ((size_t)b*NT*200 + f)*16 + p;
        if (any == 0) {
#pragma unroll
            for (int t = 0; t < NT; t++) o[(size_t)t * 3200] = a0;
        } else {
            float* hb = s_h + tid;
            for (int c = 0; c < 250; c++) {
                if (!s_flags[c]) continue;
                const int8_t* tp = s_tf + c*16;
                const float*  wp = w3 + (f*250 + c)*25;
                for (int r = r0; r <= r1; r++)
                    for (int cc = c0; cc <= c1; cc++) {
                        int tf = tp[r*4 + cc];
                        if (tf) {
                            float w = __ldg(wp + (r-(y-2))*5 + (cc-(x-2)));
                            a0 -= w;
                            if (tf < 15) hb[(tf-1)*256] += w;
                        }
                    }
            }
            float cum = a0;
#pragma unroll
            for (int t = 0; t < NT; t++) {
                if (t) cum += hb[(t-1)*256];
                o[(size_t)t * 3200] = cum;
            }
        }
    }
}

// ---------------------------------------------------------------------------
// winner: argmax over pot3[:,14] > 0 (earliest index on ties), class = feat/20.
__global__ void k_winner(const float* __restrict__ pot, float* __restrict__ cls) {
    __shared__ float s_v[256];
    __shared__ int   s_i[256];
    int b = blockIdx.x, tid = threadIdx.x;
    const float* p = pot + ((size_t)b*NT + 14) * 3200;
    float bv = 0.0f; int bi = 1 << 30;
    for (int i = tid; i < 3200; i += 256) {
        float v = p[i];
        if (v > bv) { bv = v; bi = i; }
    }
    s_v[tid] = bv; s_i[tid] = bi;
    __syncthreads();
    for (int s = 128; s > 0; s >>= 1) {
        if (tid < s) {
            float ov = s_v[tid+s]; int oi = s_i[tid+s];
            if (ov > s_v[tid] || (ov == s_v[tid] && oi < s_i[tid])) {
                s_v[tid] = ov; s_i[tid] = oi;
            }
        }
        __syncthreads();
    }
    if (tid == 0)
        cls[b] = (s_v[0] > 0.0f) ? (float)((s_i[0] >> 4) / 20) : -1.0f;
}

// ---------------------------------------------------------------------------
extern "C" void kernel_launch(void* const* d_in, const int* in_sizes, int n_in,
                              void* d_out, int out_size) {
    const float* inp = (const float*)d_in[0];
    const float* w1  = (const float*)d_in[1];
    const float* w2  = (const float*)d_in[2];
    const float* w3  = (const float*)d_in[3];

    float* out = (float*)d_out;
    float* pot = out;
    float* cls = nullptr;
    if (out_size == NB + NB*NT*3200) {   // (cls, pot3) concatenated
        cls = out;
        pot = out + NB;
    }

    k_tf0  <<<(NB*18*1024 + 255)/256, 256>>>(inp);
    k_wrep1<<<(12*882*8 + 255)/256, 256>>>(w1);
    k_wsat2<<<250, 32>>>(w2);
    k_wsat3<<<200, 32>>>(w3);
    k_conv1<<<dim3(4, 12, NB), dim3(32, 8)>>>();
    k_pool1<<<(NB*90*15*16 + 255)/256, 256>>>();
    k_conv2<<<dim3(250, NB), 192>>>(w2);
    k_pool2<<<(NB*250*16 + 255)/256, 256>>>();
    k_conv3<<<dim3(13, NB), 256>>>(w3, pot);
    if (cls) k_winner<<<NB, 256>>>(pot, cls);
}

// round 3
// speedup vs baseline: 45.6995x; 1.9983x over previous
#include <cuda_runtime.h>
#include <stdint.h>

#define NB 32
#define NT 15

// ---------------- device scratch (no cudaMalloc allowed) ----------------
static __device__ __align__(16) int8_t  g_tf0 [NB*18*32*32];   // input fire times
static __device__ __align__(16) float   g_w1q [3*882*32];      // w1: [fg][k][32 lanes]
static __device__ __align__(16) int8_t  g_ft1p[NB*90*15*16];   // pooled L1 fire times
static __device__              uint8_t g_cflag1[NB*90];
static __device__              int     g_any1[NB];
static __device__ __align__(16) int8_t  g_ft2p[NB*250*16];     // pooled L2 fire times
static __device__              uint8_t g_cflag2[NB*250];
static __device__              int     g_any2[NB];
static __device__              float   g_wsat2[250*36];        // SAT of channel-summed w2
static __device__              float   g_wsat3[200*36];        // SAT of channel-summed w3

// ===========================================================================
// k_prep: fused weight-SAT (deterministic), w1 repack, input fire-times,
// and flag zeroing. Block ranges: [0,250) wsat2, [250,450) wsat3,
// [450,781) wrep, [781,3085) tf0, [3085] zero flags.
__global__ __launch_bounds__(256) void k_prep(const float* __restrict__ inp,
                                              const float* __restrict__ w1,
                                              const float* __restrict__ w2,
                                              const float* __restrict__ w3) {
    int bid = blockIdx.x, tid = threadIdx.x;
    if (bid < 450) {
        __shared__ float s_part[250];
        __shared__ float s25[25];
        const float* src; int C; float* dst; int f;
        if (bid < 250) { f = bid;     src = w2; C = 90;  dst = g_wsat2 + f*36; }
        else           { f = bid-250; src = w3; C = 250; dst = g_wsat3 + f*36; }
        if (tid < 250) {
            int p = tid / 10, g = tid % 10;
            float s = 0.0f;
            for (int c = g; c < C; c += 10) s += src[((size_t)f*C + c)*25 + p];
            s_part[p*10 + g] = s;
        }
        __syncthreads();
        if (tid < 25) {
            float s = 0.0f;
            for (int g = 0; g < 10; g++) s += s_part[tid*10 + g];
            s25[tid] = s;
        }
        __syncthreads();
        if (tid < 36) {
            int i = tid / 6, j = tid % 6;
            float s = 0.0f;
            for (int ii = 0; ii < i; ii++)
                for (int jj = 0; jj < j; jj++) s += s25[ii*5 + jj];
            dst[tid] = s;
        }
    } else if (bid < 781) {
        int idx = (bid - 450)*256 + tid;
        if (idx < 3*882*32) {
            int lane = idx & 31, k = (idx >> 5) % 882, fg = idx / (882*32);
            int f = fg*32 + lane;
            g_w1q[idx] = (f < 90) ? w1[f*882 + k] : 0.0f;
        }
    } else if (bid < 3085) {
        int idx = (bid - 781)*256 + tid;          // < 32*18*1024 exactly
        int b   = idx / (18*1024);
        int chw = idx - b*(18*1024);
        const float* p = inp + (size_t)b*(NT*18*1024) + chw;
        float s = 0.0f;
#pragma unroll
        for (int t = 0; t < NT; t++) s += p[(size_t)t * 18 * 1024];
        g_tf0[idx] = (int8_t)(15 - (int)(s + 0.5f));
    } else {
        for (int i = tid; i < NB*90;  i += 256) g_cflag1[i] = 0;
        for (int i = tid; i < NB*250; i += 256) g_cflag2[i] = 0;
        if (tid < NB) { g_any1[tid] = 0; g_any2[tid] = 0; }
    }
}

// ===========================================================================
// conv1 slow path (essentially never taken with this data): full per-t scan.
__device__ __noinline__ int conv1_slow(const float* __restrict__ w1,
                                       int b, int f, int y, int x) {
    const int8_t* tf = g_tf0 + (size_t)b*18*1024;
    const float* wf = w1 + (size_t)f*882;
    for (int t = 1; t < 15; t++) {
        float cum = 0.0f;
        for (int c = 0; c < 18; c++)
            for (int i = 0; i < 7; i++) {
                int h = y + i - 2;
                if ((unsigned)h >= 32u) continue;
                for (int j = 0; j < 7; j++) {
                    int w = x + j - 2;
                    if ((unsigned)w >= 32u) continue;
                    if (tf[(c << 10) + (h << 5) + w] <= t) cum += wf[c*49 + i*7 + j];
                }
            }
        if (cum > 15.0f) return t;
    }
    return 15;
}

// ===========================================================================
// conv1: lane=filter (32 per warp), warp = 4 adjacent output pixels.
// Warp-uniform bitmask iteration over tf==0 taps. Fused 2x2 pool + flags.
// grid (8 row-quads, 3 fgroups, 32 b), 1024 threads, dynamic smem:
//   s_w [882*32] f32 | s_m [18*10] u64 | s_ft [4*32*32] i8
#define CONV1_SMEM (882*32*4 + 180*8 + 4096)
extern __shared__ unsigned char smem_raw[];
__global__ __launch_bounds__(1024, 1) void k_conv1(const float* __restrict__ w1) {
    float*    s_w  = (float*)smem_raw;
    uint64_t* s_m  = (uint64_t*)(smem_raw + 882*32*4);
    int8_t*   s_ft = (int8_t*)(smem_raw + 882*32*4 + 180*8);
    int tid = threadIdx.x;
    int rq = blockIdx.x, fg = blockIdx.y, b = blockIdx.z;
    int lane = tid & 31, w = tid >> 5;

    // weights for this 32-filter group
    const uint4* wsrc = (const uint4*)(g_w1q + (size_t)fg*882*32);
    uint4* wdst = (uint4*)s_w;
    for (int i = tid; i < 882*32/4; i += 1024) wdst[i] = wsrc[i];
    // row bitmasks: bit (w_in+2) set iff tf==0
    if (tid < 180) {
        int c = tid / 10, rr = tid % 10;
        int h = rq*4 + rr - 2;
        uint64_t mask = 0;
        if ((unsigned)h < 32u) {
            const uint32_t* row = (const uint32_t*)(g_tf0 + ((b*18 + c) << 10) + (h << 5));
            uint32_t bits = 0;
#pragma unroll
            for (int k2 = 0; k2 < 8; k2++) {
                uint32_t nib = ((__vseteq4(row[k2], 0u) * 0x01020408u) >> 24) & 0xFu;
                bits |= nib << (k2*4);
            }
            mask = ((uint64_t)bits) << 2;
        }
        s_m[c*10 + rr] = mask;
    }
    __syncthreads();

    int dy = w >> 3, q = w & 7;
    int y = rq*4 + dy, x0 = q*4;
    float a0 = 0.f, a1 = 0.f, a2 = 0.f, a3 = 0.f;
    if (y < 30) {
        for (int c = 0; c < 18; c++) {
            const uint64_t* mrow = s_m + c*10 + dy;
            const float* wc = s_w + c*49*32 + lane;
#pragma unroll
            for (int i = 0; i < 7; i++) {
                uint32_t wnd = (uint32_t)(mrow[i] >> x0) & 0x3FFu;  // bits p: j=p-k
                const float* wi = wc + i*7*32;
                while (wnd) {
                    int p = __ffs(wnd) - 1;
                    wnd &= wnd - 1;
                    if (p <= 6)           a0 += wi[p*32];
                    if (p >= 1 && p <= 7) a1 += wi[(p-1)*32];
                    if (p >= 2 && p <= 8) a2 += wi[(p-2)*32];
                    if (p >= 3)           a3 += wi[(p-3)*32];
                }
            }
        }
    }
    int f = fg*32 + lane;
    float aa[4] = {a0, a1, a2, a3};
#pragma unroll
    for (int k = 0; k < 4; k++) {
        int x = x0 + k;
        int ft = 0;
        if (y < 30 && x < 30 && f < 90)
            ft = (aa[k] > 15.0f) ? 0 : conv1_slow(w1, b, f, y, x);
        s_ft[(dy*32 + x)*32 + lane] = (int8_t)ft;
    }
    __syncthreads();

    // fused 2x2 pool (min of fire times) + channel flags
    bool nz = false;
    if (tid < 960) {
        int pf = tid & 31;
        int rest = tid >> 5;            // 0..29
        int pcol = rest % 15;
        int pr   = rest / 15;           // 0..1
        int prow = rq*2 + pr;
        int r0 = pr*2, c0 = pcol*2;
        int v0 = s_ft[(r0*32     + c0  )*32 + pf];
        int v1 = s_ft[(r0*32     + c0+1)*32 + pf];
        int v2 = s_ft[((r0+1)*32 + c0  )*32 + pf];
        int v3 = s_ft[((r0+1)*32 + c0+1)*32 + pf];
        int m0 = v0 < v1 ? v0 : v1;
        int m1 = v2 < v3 ? v2 : v3;
        int pv = m0 < m1 ? m0 : m1;
        int ff = fg*32 + pf;
        if (prow < 15 && ff < 90) {
            g_ft1p[((b*90 + ff)*15 + prow)*16 + pcol] = (int8_t)pv;
            if (pv) { g_cflag1[b*90 + ff] = 1; nz = true; }
        }
    }
    int cnt = __syncthreads_count(nz);
    if (tid == 0 && cnt) atomicAdd(&g_any1[b], 1);
}

// ===========================================================================
// conv2: SAT fast path (skips ALL tile loads when batch is all-zero),
// per-channel corrections otherwise. Fused 3x3 pool + layer-2 flags.
__global__ __launch_bounds__(192) void k_conv2(const float* __restrict__ w2) {
    __shared__ __align__(16) int8_t s_tf[90*240];
    __shared__ float   s_sat[36];
    __shared__ float   s_h[14*192];
    __shared__ uint8_t s_flags[90];
    __shared__ int8_t  s_ftp[169];
    int tid = threadIdx.x;
    int f = blockIdx.x, b = blockIdx.y;
    int any = g_any1[b];

    if (tid < 36) s_sat[tid] = g_wsat2[f*36 + tid];
    if (any) {
        const uint4* src = (const uint4*)(g_ft1p + (size_t)b*90*240);
        uint4* dst = (uint4*)s_tf;
        for (int i = tid; i < 90*240/16; i += 192) dst[i] = src[i];
        if (tid < 90) s_flags[tid] = g_cflag1[b*90 + tid];
        for (int t = 0; t < 14; t++) s_h[t*192 + tid] = 0.0f;
    }
    __syncthreads();

    if (tid < 169) {
        int y = tid / 13, x = tid - y*13;
        int r0 = max(0, y-1), r1 = min(14, y+3);
        int c0 = max(0, x-1), c1 = min(14, x+3);
        int i0 = r0 - (y-1), i1 = r1 - (y-1);
        int j0 = c0 - (x-1), j1 = c1 - (x-1);
        float a0 = s_sat[(i1+1)*6 + (j1+1)] - s_sat[i0*6 + (j1+1)]
                 - s_sat[(i1+1)*6 + j0]     + s_sat[i0*6 + j0];
        int ft;
        if (!any) {
            ft = (a0 > 10.0f) ? 0 : 15;
        } else {
            float* hb = s_h + tid;
            for (int c = 0; c < 90; c++) {
                if (!s_flags[c]) continue;
                const int8_t* tp = s_tf + c*240;
                const float*  wp = w2 + ((size_t)f*90 + c)*25;
                for (int r = r0; r <= r1; r++)
                    for (int cc = c0; cc <= c1; cc++) {
                        int tf = tp[r*16 + cc];
                        if (tf) {
                            float wv = __ldg(wp + (r-(y-1))*5 + (cc-(x-1)));
                            a0 -= wv;
                            if (tf < 15) hb[(tf-1)*192] += wv;
                        }
                    }
            }
            float cum = a0; ft = 15;
            if (cum > 10.0f) ft = 0;
#pragma unroll
            for (int t = 1; t < 15; t++) {
                cum += hb[(t-1)*192];
                if (ft == 15 && cum > 10.0f) ft = t;
            }
        }
        s_ftp[tid] = (int8_t)ft;
    }
    __syncthreads();

    bool nz = false;
    if (tid < 16) {
        int yy = tid >> 2, xx = tid & 3;
        const int8_t* bp = s_ftp + yy*39 + xx*3;
        int v = 15;
#pragma unroll
        for (int dy = 0; dy < 3; dy++)
#pragma unroll
            for (int dx = 0; dx < 3; dx++) {
                int u = bp[dy*13 + dx];
                v = u < v ? u : v;
            }
        g_ft2p[(b*250 + f)*16 + tid] = (int8_t)v;
        nz = (v != 0);
    }
    int cnt = __syncthreads_count(nz);
    if (tid == 0 && cnt) { g_cflag2[b*250 + f] = 1; atomicAdd(&g_any2[b], 1); }
}

// ===========================================================================
// conv3: SAT fast path (skip tile loads if any2==0), else corrections + hist.
__global__ __launch_bounds__(256) void k_conv3(const float* __restrict__ w3,
                                               float* __restrict__ pot) {
    __shared__ __align__(16) int8_t s_tf[250*16];
    __shared__ float   s_sat[16*36];
    __shared__ float   s_h[14*256];
    __shared__ uint8_t s_flags[250];
    int tid = threadIdx.x;
    int fg = blockIdx.x, b = blockIdx.y;
    int any = g_any2[b];

    for (int i = tid; i < 16*36; i += 256) {
        int f = fg*16 + i/36;
        s_sat[i] = (f < 200) ? g_wsat3[f*36 + i%36] : 0.0f;
    }
    if (any) {
        const uint4* src = (const uint4*)(g_ft2p + (size_t)b*250*16);
        for (int i = tid; i < 250; i += 256) ((uint4*)s_tf)[i] = src[i];
        if (tid < 250) s_flags[tid] = g_cflag2[b*250 + tid];
        for (int t = 0; t < 14; t++) s_h[t*256 + tid] = 0.0f;
    }
    __syncthreads();

    int fi = tid >> 4, p = tid & 15;
    int f = fg*16 + fi;
    if (f < 200) {
        int y = p >> 2, x = p & 3;
        int r0 = max(0, y-2), r1 = min(3, y+2);
        int c0 = max(0, x-2), c1 = min(3, x+2);
        int i0 = r0 - (y-2), i1 = r1 - (y-2);
        int j0 = c0 - (x-2), j1 = c1 - (x-2);
        const float* S = s_sat + fi*36;
        float a0 = S[(i1+1)*6 + (j1+1)] - S[i0*6 + (j1+1)]
                 - S[(i1+1)*6 + j0]     + S[i0*6 + j0];
        float* o = pot + ((size_t)b*NT*200 + f)*16 + p;
        if (!any) {
#pragma unroll
            for (int t = 0; t < NT; t++) o[(size_t)t * 3200] = a0;
        } else {
            float* hb = s_h + tid;
            for (int c = 0; c < 250; c++) {
                if (!s_flags[c]) continue;
                const int8_t* tp = s_tf + c*16;
                const float*  wp = w3 + ((size_t)f*250 + c)*25;
                for (int r = r0; r <= r1; r++)
                    for (int cc = c0; cc <= c1; cc++) {
                        int tf = tp[r*4 + cc];
                        if (tf) {
                            float wv = __ldg(wp + (r-(y-2))*5 + (cc-(x-2)));
                            a0 -= wv;
                            if (tf < 15) hb[(tf-1)*256] += wv;
                        }
                    }
            }
            float cum = a0;
#pragma unroll
            for (int t = 0; t < NT; t++) {
                if (t) cum += hb[(t-1)*256];
                o[(size_t)t * 3200] = cum;
            }
        }
    }
}

// ===========================================================================
// winner: argmax over pot3[:,14] > 0 (earliest index on ties), class = feat/20.
__global__ void k_winner(const float* __restrict__ pot, float* __restrict__ cls) {
    __shared__ float s_v[256];
    __shared__ int   s_i[256];
    int b = blockIdx.x, tid = threadIdx.x;
    const float* p = pot + ((size_t)b*NT + 14) * 3200;
    float bv = 0.0f; int bi = 1 << 30;
    for (int i = tid; i < 3200; i += 256) {
        float v = p[i];
        if (v > bv) { bv = v; bi = i; }
    }
    s_v[tid] = bv; s_i[tid] = bi;
    __syncthreads();
    for (int s = 128; s > 0; s >>= 1) {
        if (tid < s) {
            float ov = s_v[tid+s]; int oi = s_i[tid+s];
            if (ov > s_v[tid] || (ov == s_v[tid] && oi < s_i[tid])) {
                s_v[tid] = ov; s_i[tid] = oi;
            }
        }
        __syncthreads();
    }
    if (tid == 0)
        cls[b] = (s_v[0] > 0.0f) ? (float)((s_i[0] >> 4) / 20) : -1.0f;
}

// ===========================================================================
extern "C" void kernel_launch(void* const* d_in, const int* in_sizes, int n_in,
                              void* d_out, int out_size) {
    const float* inp = (const float*)d_in[0];
    const float* w1  = (const float*)d_in[1];
    const float* w2  = (const float*)d_in[2];
    const float* w3  = (const float*)d_in[3];

    float* out = (float*)d_out;
    float* pot = out;
    float* cls = nullptr;
    if (out_size == NB + NB*NT*3200) {   // (cls, pot3) concatenated
        cls = out;
        pot = out + NB;
    }

    static bool attr_set = false;
    if (!attr_set) {
        cudaFuncSetAttribute(k_conv1, cudaFuncAttributeMaxDynamicSharedMemorySize,
                             CONV1_SMEM);
        attr_set = true;
    }

    k_prep <<<3086, 256>>>(inp, w1, w2, w3);
    k_conv1<<<dim3(8, 3, NB), 1024, CONV1_SMEM>>>(w1);
    k_conv2<<<dim3(250, NB), 192>>>(w2);
    k_conv3<<<dim3(13, NB), 256>>>(w3, pot);
    if (cls) k_winner<<<NB, 256>>>(pot, cls);
}